// round 1
// baseline (speedup 1.0000x reference)
#include <cuda_runtime.h>
#include <math.h>

#define BATCH 32
#define HH 256
#define WW 256
#define NPIX (BATCH*HH*WW)
#define NROWS (BATCH*HH)
#define INF_D 1e4f
#define RED_BLOCKS 2048

// ---------------- scratch (no allocations allowed) ----------------
__device__ unsigned char g_hd[NPIX];
__device__ unsigned char g_fat[NPIX];
__device__ float g_gv[NPIX];      // vertical distance, then squared
__device__ float g_soft[NPIX];
__device__ float g_rowmin[NROWS];
__device__ float g_rowmax[NROWS];
__device__ int   g_rowfg[NROWS];
__device__ float g_mn[BATCH];
__device__ float g_inv[BATCH];
__device__ int   g_fg[BATCH];
__device__ float g_pinter[RED_BLOCKS];
__device__ float g_pcard[RED_BLOCKS];
__device__ float g_ptsum[RED_BLOCKS];

// ---------------- K1: horizontal 5-dilate ----------------
__global__ void k_hdil(const float* __restrict__ tg) {
    int idx = blockIdx.x * blockDim.x + threadIdx.x;
    if (idx >= NPIX) return;
    int w = idx & (WW - 1);
    unsigned char v = 0;
#pragma unroll
    for (int o = -2; o <= 2; o++) {
        int ww = w + o;
        if (ww >= 0 && ww < WW) v |= (tg[idx + o] > 0.5f) ? 1 : 0;
    }
    g_hd[idx] = v;
}

// ---------------- K2: vertical 5-dilate ----------------
__global__ void k_vdil() {
    int idx = blockIdx.x * blockDim.x + threadIdx.x;
    if (idx >= NPIX) return;
    int h = (idx >> 8) & (HH - 1);
    unsigned char v = 0;
#pragma unroll
    for (int o = -2; o <= 2; o++) {
        int hh = h + o;
        if (hh >= 0 && hh < HH) v |= g_hd[idx + o * WW];
    }
    g_fat[idx] = v;
}

// ---------------- K3: vertical distance (two-pass scan per column) ----------------
__global__ void k_vdist() {
    int t = blockIdx.x * blockDim.x + threadIdx.x;   // 0 .. BATCH*WW-1
    if (t >= BATCH * WW) return;
    int b = t >> 8;
    int w = t & (WW - 1);
    int base = b * HH * WW + w;
    float d = INF_D;
    for (int h = 0; h < HH; h++) {
        int a = base + h * WW;
        d = g_fat[a] ? fminf(d + 1.0f, INF_D) : 0.0f;
        g_gv[a] = d;
    }
    d = INF_D;
    for (int h = HH - 1; h >= 0; h--) {
        int a = base + h * WW;
        d = g_fat[a] ? fminf(d + 1.0f, INF_D) : 0.0f;
        float g = fminf(g_gv[a], d);
        g_gv[a] = g * g;
    }
}

// ---------------- K4: horizontal min-plus (pruned) + soft + row reductions ----------------
__global__ void k_hpass(const float* __restrict__ tg) {
    __shared__ float sg[WW];
    __shared__ float smin[WW];
    __shared__ float smax[WW];
    __shared__ int   sfg[WW];
    int row = blockIdx.x;            // b*HH + i
    int j = threadIdx.x;
    int base = row * WW;
    float g2 = g_gv[base + j];
    sg[j] = g2;
    float t = tg[base + j];
    __syncthreads();

    float best = g2;
    for (int rad = 1; rad < WW; rad++) {
        float r2 = (float)(rad * rad);
        if (r2 >= best) break;
        int jl = j - rad, jr = j + rad;
        if (jl >= 0) best = fminf(best, sg[jl] + r2);
        if (jr < WW) best = fminf(best, sg[jr] + r2);
    }
    float dist = sqrtf(best);
    float soft = 1.0f / (1.0f + __expf(-dist * 0.2f));
    g_soft[base + j] = soft;

    smin[j] = soft; smax[j] = soft; sfg[j] = (t > 0.5f) ? 1 : 0;
    __syncthreads();
#pragma unroll
    for (int s = 128; s > 0; s >>= 1) {
        if (j < s) {
            smin[j] = fminf(smin[j], smin[j + s]);
            smax[j] = fmaxf(smax[j], smax[j + s]);
            sfg[j] |= sfg[j + s];
        }
        __syncthreads();
    }
    if (j == 0) {
        g_rowmin[row] = smin[0];
        g_rowmax[row] = smax[0];
        g_rowfg[row]  = sfg[0];
    }
}

// ---------------- K5: per-image reduce of row stats ----------------
__global__ void k_imgred() {
    __shared__ float smin[HH];
    __shared__ float smax[HH];
    __shared__ int   sfg[HH];
    int b = blockIdx.x;
    int j = threadIdx.x;
    int r = b * HH + j;
    smin[j] = g_rowmin[r]; smax[j] = g_rowmax[r]; sfg[j] = g_rowfg[r];
    __syncthreads();
#pragma unroll
    for (int s = 128; s > 0; s >>= 1) {
        if (j < s) {
            smin[j] = fminf(smin[j], smin[j + s]);
            smax[j] = fmaxf(smax[j], smax[j + s]);
            sfg[j] |= sfg[j + s];
        }
        __syncthreads();
    }
    if (j == 0) {
        float mn = smin[0];
        float dd = smax[0] - mn;
        g_mn[b]  = mn;
        g_inv[b] = (dd > 0.0f) ? (1.0f / dd) : 1.0f;
        g_fg[b]  = sfg[0];
    }
}

// ---------------- K6: fused sigmoid * dm * dice partials ----------------
__global__ void k_final(const float* __restrict__ preds, const float* __restrict__ tg) {
    __shared__ float si[256];
    __shared__ float sc[256];
    __shared__ float st[256];
    int tid = blockIdx.x * blockDim.x + threadIdx.x;
    int stride = gridDim.x * blockDim.x;
    float inter = 0.0f, card = 0.0f, tsum = 0.0f;
    for (int idx = tid; idx < NPIX; idx += stride) {
        int b = idx >> 16;
        float t = tg[idx];
        float p = 1.0f / (1.0f + __expf(-preds[idx]));
        float dm;
        if (g_fg[b]) {
            dm = (g_soft[idx] - g_mn[b]) * g_inv[b] + (1.0f - (float)g_fat[idx]) * 0.1f;
        } else {
            dm = 1.0f - t;
        }
        float pw = p * dm;
        inter += pw * t;
        card  += pw + t;
        tsum  += t;
    }
    si[threadIdx.x] = inter; sc[threadIdx.x] = card; st[threadIdx.x] = tsum;
    __syncthreads();
#pragma unroll
    for (int s = 128; s > 0; s >>= 1) {
        if (threadIdx.x < s) {
            si[threadIdx.x] += si[threadIdx.x + s];
            sc[threadIdx.x] += sc[threadIdx.x + s];
            st[threadIdx.x] += st[threadIdx.x + s];
        }
        __syncthreads();
    }
    if (threadIdx.x == 0) {
        g_pinter[blockIdx.x] = si[0];
        g_pcard[blockIdx.x]  = sc[0];
        g_ptsum[blockIdx.x]  = st[0];
    }
}

// ---------------- K7: final deterministic sum + loss ----------------
__global__ void k_out(float* out) {
    __shared__ float si[256];
    __shared__ float sc[256];
    __shared__ float st[256];
    int j = threadIdx.x;
    float inter = 0.0f, card = 0.0f, tsum = 0.0f;
    for (int k = j; k < RED_BLOCKS; k += 256) {
        inter += g_pinter[k];
        card  += g_pcard[k];
        tsum  += g_ptsum[k];
    }
    si[j] = inter; sc[j] = card; st[j] = tsum;
    __syncthreads();
#pragma unroll
    for (int s = 128; s > 0; s >>= 1) {
        if (j < s) {
            si[j] += si[j + s];
            sc[j] += sc[j + s];
            st[j] += st[j + s];
        }
        __syncthreads();
    }
    if (j == 0) {
        float dice = 2.0f * si[0] / fmaxf(sc[0], 1e-7f);
        float loss = 1.0f - dice;
        out[0] = (st[0] > 0.0f) ? loss : 0.0f;
    }
}

extern "C" void kernel_launch(void* const* d_in, const int* in_sizes, int n_in,
                              void* d_out, int out_size) {
    const float* preds = (const float*)d_in[0];
    const float* tg    = (const float*)d_in[1];
    float* out = (float*)d_out;

    k_hdil<<<NPIX / 256, 256>>>(tg);
    k_vdil<<<NPIX / 256, 256>>>();
    k_vdist<<<(BATCH * WW) / 256, 256>>>();
    k_hpass<<<NROWS, WW>>>(tg);
    k_imgred<<<BATCH, HH>>>();
    k_final<<<RED_BLOCKS, 256>>>(preds, tg);
    k_out<<<1, 256>>>(out);
}

// round 2
// speedup vs baseline: 1.5430x; 1.5430x over previous
#include <cuda_runtime.h>
#include <math.h>

#define BATCH 32
#define HH 256
#define WW 256
#define IMGPIX (HH*WW)                 // 65536
#define NPIX (BATCH*IMGPIX)
#define NTHREADS 1024
#define PIX_PER_THREAD (IMGPIX/NTHREADS)   // 64
#define INF_I 10000

// dynamic shared layout (bytes):
//   [0,      8192)   tgmask  : 2048 u32  (target bits, row-major, 8 words/row)
//   [8192,  16384)   hmask   : 2048 u32  (horizontal dilation)
//   [16384, 24576)   fatmask : 2048 u32  (full 5x5 dilation)
//   [24576, 155648)  g       : 65536 u16 (vertical distance, row-major)
#define SM_TG   0
#define SM_HM   2048
#define SM_FAT  4096
#define SM_G    (24576/2)              // offset in u16 units
#define SMEM_BYTES (24576 + 131072)

__device__ float g_pinter[BATCH];
__device__ float g_pcard[BATCH];
__device__ float g_ptsum[BATCH];

__device__ __forceinline__ float fwarpRedSum(float v) {
#pragma unroll
    for (int s = 16; s > 0; s >>= 1) v += __shfl_down_sync(0xffffffffu, v, s);
    return v;
}
__device__ __forceinline__ int iwarpRedMin(int v) {
#pragma unroll
    for (int s = 16; s > 0; s >>= 1) v = min(v, __shfl_down_sync(0xffffffffu, v, s));
    return v;
}
__device__ __forceinline__ int iwarpRedMax(int v) {
#pragma unroll
    for (int s = 16; s > 0; s >>= 1) v = max(v, __shfl_down_sync(0xffffffffu, v, s));
    return v;
}

// pruned horizontal min-plus for one pixel (row r, col j); g row in u16 SMEM
__device__ __forceinline__ int best_d2(const unsigned short* __restrict__ g, int r, int j) {
    const unsigned short* grow = g + r * WW;
    int g0 = grow[j];
    int best = g0 * g0;
#pragma unroll 4
    for (int rad = 1; rad < WW; rad++) {
        int r2 = rad * rad;
        if (r2 >= best) break;
        int jl = j - rad, jr = j + rad;
        if (jl >= 0) { int gv = grow[jl]; best = min(best, gv * gv + r2); }
        if (jr < WW) { int gv = grow[jr]; best = min(best, gv * gv + r2); }
    }
    return best;
}

__global__ __launch_bounds__(NTHREADS, 1)
void k_mega(const float* __restrict__ preds, const float* __restrict__ tg) {
    extern __shared__ unsigned int smem_u32[];
    unsigned int* tgmask = smem_u32 + SM_TG;
    unsigned int* hmask  = smem_u32 + SM_HM;
    unsigned int* fatmask = smem_u32 + SM_FAT;
    unsigned short* g = reinterpret_cast<unsigned short*>(smem_u32) ;
    g = reinterpret_cast<unsigned short*>(smem_u32) + SM_G;

    __shared__ unsigned int s_fg;
    __shared__ int s_imin[32], s_imax[32];
    __shared__ float s_f[32];
    __shared__ float s_mn, s_inv;
    __shared__ int s_hasfg;

    const int tid = threadIdx.x;
    const int lane = tid & 31;
    const int wid = tid >> 5;
    const int imgbase = blockIdx.x * IMGPIX;

    if (tid == 0) s_fg = 0u;
    __syncthreads();

    // ---- phase 1: build target bitmask (coalesced + ballot) ----
    {
        unsigned int fgacc = 0u;
#pragma unroll
        for (int k = 0; k < 64; k++) {
            int widx = wid * 64 + k;                 // word index 0..2047
            int row = widx >> 3, wc = widx & 7;
            int col = wc * 32 + lane;
            float v = tg[imgbase + row * WW + col];
            unsigned int word = __ballot_sync(0xffffffffu, v > 0.5f);
            if (lane == 0) { tgmask[widx] = word; fgacc |= word; }
        }
        if (lane == 0 && fgacc) atomicOr(&s_fg, 1u);
    }
    __syncthreads();

    // ---- phase 2a: horizontal 5-dilate (bitwise) ----
#pragma unroll
    for (int p = 0; p < 2; p++) {
        int widx = tid + p * NTHREADS;
        int wc = widx & 7;
        unsigned int c  = tgmask[widx];
        unsigned int ml = (wc > 0) ? tgmask[widx - 1] : 0u;
        unsigned int mr = (wc < 7) ? tgmask[widx + 1] : 0u;
        unsigned int h = c;
        h |= (c << 1) | (ml >> 31);
        h |= (c << 2) | (ml >> 30);
        h |= (c >> 1) | (mr << 31);
        h |= (c >> 2) | (mr << 30);
        hmask[widx] = h;
    }
    __syncthreads();

    // ---- phase 2b: vertical 5-dilate ----
#pragma unroll
    for (int p = 0; p < 2; p++) {
        int widx = tid + p * NTHREADS;
        int row = widx >> 3;
        unsigned int f = hmask[widx];
        if (row >= 1)      f |= hmask[widx - 8];
        if (row >= 2)      f |= hmask[widx - 16];
        if (row <= HH - 2) f |= hmask[widx + 8];
        if (row <= HH - 3) f |= hmask[widx + 16];
        fatmask[widx] = f;
    }
    __syncthreads();

    // ---- phase 3: vertical distance scan per column (SMEM only) ----
    if (tid < WW) {
        const int j = tid;
        const int wsel = j >> 5, bsel = j & 31;
        int d = INF_I;
        for (int h = 0; h < HH; h++) {
            unsigned int fw = fatmask[(h << 3) | wsel];
            int bit = (fw >> bsel) & 1u;
            d = bit ? min(d + 1, INF_I) : 0;
            g[h * WW + j] = (unsigned short)d;
        }
        d = INF_I;
        for (int h = HH - 1; h >= 0; h--) {
            unsigned int fw = fatmask[(h << 3) | wsel];
            int bit = (fw >> bsel) & 1u;
            d = bit ? min(d + 1, INF_I) : 0;
            int cur = g[h * WW + j];
            g[h * WW + j] = (unsigned short)min(cur, d);
        }
    }
    __syncthreads();

    // ---- phase 4a: image min/max of d^2 (for soft normalization) ----
    {
        int minb = 0x7fffffff, maxb = 0;
#pragma unroll 1
        for (int k = 0; k < PIX_PER_THREAD; k++) {
            int idx = tid + k * NTHREADS;
            int r = idx >> 8, j = idx & (WW - 1);
            int best = best_d2(g, r, j);
            minb = min(minb, best);
            maxb = max(maxb, best);
        }
        minb = iwarpRedMin(minb);
        maxb = iwarpRedMax(maxb);
        if (lane == 0) { s_imin[wid] = minb; s_imax[wid] = maxb; }
        __syncthreads();
        if (tid == 0) {
            int mn = s_imin[0], mx = s_imax[0];
#pragma unroll
            for (int i = 1; i < 32; i++) { mn = min(mn, s_imin[i]); mx = max(mx, s_imax[i]); }
            float smn = 1.0f / (1.0f + __expf(-sqrtf((float)mn) * 0.2f));
            float smx = 1.0f / (1.0f + __expf(-sqrtf((float)mx) * 0.2f));
            float dd = smx - smn;
            s_mn = smn;
            s_inv = (dd > 0.0f) ? (1.0f / dd) : 1.0f;
            s_hasfg = (s_fg != 0u) ? 1 : 0;
        }
        __syncthreads();
    }

    // ---- phase 5: fused dm + dice partials ----
    {
        const float mn = s_mn, inv = s_inv;
        const int hasfg = s_hasfg;
        float inter = 0.0f, card = 0.0f, tsum = 0.0f;
#pragma unroll 1
        for (int k = 0; k < PIX_PER_THREAD; k++) {
            int idx = tid + k * NTHREADS;
            int r = idx >> 8, j = idx & (WW - 1);
            int wsel = (idx >> 5);
            int bsel = idx & 31;
            float t = (float)((tgmask[wsel] >> bsel) & 1u);
            float p = 1.0f / (1.0f + __expf(-preds[imgbase + idx]));
            float dm;
            if (hasfg) {
                int best = best_d2(g, r, j);
                float dist = sqrtf((float)best);
                float soft = 1.0f / (1.0f + __expf(-dist * 0.2f));
                float fatb = (float)((fatmask[wsel] >> bsel) & 1u);
                dm = (soft - mn) * inv + (1.0f - fatb) * 0.1f;
            } else {
                dm = 1.0f - t;
            }
            float pw = p * dm;
            inter += pw * t;
            card  += pw + t;
            tsum  += t;
        }
        // block reduce (deterministic tree)
        inter = fwarpRedSum(inter);
        if (lane == 0) s_f[wid] = inter;
        __syncthreads();
        if (tid == 0) {
            float a = 0.0f;
#pragma unroll
            for (int i = 0; i < 32; i++) a += s_f[i];
            g_pinter[blockIdx.x] = a;
        }
        __syncthreads();
        card = fwarpRedSum(card);
        if (lane == 0) s_f[wid] = card;
        __syncthreads();
        if (tid == 0) {
            float a = 0.0f;
#pragma unroll
            for (int i = 0; i < 32; i++) a += s_f[i];
            g_pcard[blockIdx.x] = a;
        }
        __syncthreads();
        tsum = fwarpRedSum(tsum);
        if (lane == 0) s_f[wid] = tsum;
        __syncthreads();
        if (tid == 0) {
            float a = 0.0f;
#pragma unroll
            for (int i = 0; i < 32; i++) a += s_f[i];
            g_ptsum[blockIdx.x] = a;
        }
    }
}

__global__ void k_out(float* out) {
    int j = threadIdx.x;
    float inter = (j < BATCH) ? g_pinter[j] : 0.0f;
    float card  = (j < BATCH) ? g_pcard[j]  : 0.0f;
    float tsum  = (j < BATCH) ? g_ptsum[j]  : 0.0f;
    inter = fwarpRedSum(inter);
    card  = fwarpRedSum(card);
    tsum  = fwarpRedSum(tsum);
    if (j == 0) {
        float dice = 2.0f * inter / fmaxf(card, 1e-7f);
        float loss = 1.0f - dice;
        out[0] = (tsum > 0.0f) ? loss : 0.0f;
    }
}

extern "C" void kernel_launch(void* const* d_in, const int* in_sizes, int n_in,
                              void* d_out, int out_size) {
    const float* preds = (const float*)d_in[0];
    const float* tg    = (const float*)d_in[1];
    float* out = (float*)d_out;

    cudaFuncSetAttribute(k_mega, cudaFuncAttributeMaxDynamicSharedMemorySize, SMEM_BYTES);
    k_mega<<<BATCH, NTHREADS, SMEM_BYTES>>>(preds, tg);
    k_out<<<1, 32>>>(out);
}

// round 3
// speedup vs baseline: 2.8374x; 1.8389x over previous
#include <cuda_runtime.h>
#include <math.h>

#define BATCH 32
#define HH 256
#define WW 256
#define IMGPIX 65536
#define NPIX (BATCH*IMGPIX)
#define IMGWORDS (IMGPIX/32)     // 2048
#define NWORDS (NPIX/32)
#define INF_I 10000
#define DICE_BLOCKS 2048
#define ROW_BLOCKS 256           // 32 images x 8 bands of 32 rows

__device__ unsigned int  g_tgm[NWORDS];
__device__ unsigned int  g_fatm[NWORDS];
__device__ unsigned short g_gv[NPIX];
__device__ unsigned int  g_d2[NPIX];
__device__ int   g_bmin[ROW_BLOCKS];
__device__ int   g_bmax[ROW_BLOCKS];
__device__ int   g_fg[BATCH];
__device__ float g_pi[DICE_BLOCKS], g_pc[DICE_BLOCKS], g_pt[DICE_BLOCKS];

__device__ __forceinline__ float fsum32(float v) {
#pragma unroll
    for (int s = 16; s > 0; s >>= 1) v += __shfl_down_sync(0xffffffffu, v, s);
    return v;
}
__device__ __forceinline__ int imin32(int v) {
#pragma unroll
    for (int s = 16; s > 0; s >>= 1) v = min(v, __shfl_down_sync(0xffffffffu, v, s));
    return v;
}
__device__ __forceinline__ int imax32(int v) {
#pragma unroll
    for (int s = 16; s > 0; s >>= 1) v = max(v, __shfl_down_sync(0xffffffffu, v, s));
    return v;
}
__device__ __forceinline__ unsigned int ior32(unsigned int v) {
#pragma unroll
    for (int s = 16; s > 0; s >>= 1) v |= __shfl_down_sync(0xffffffffu, v, s);
    return v;
}

// ---- K1: bitmask build + bitwise 5x5 dilation (512 blocks x 256 thr) ----
__global__ void k_dilate(const float* __restrict__ tg) {
    __shared__ unsigned int tgw[20 * 8];
    __shared__ unsigned int hw[20 * 8];
    const int tid = threadIdx.x;
    const int lane = tid & 31, wid = tid >> 5;   // 8 warps = 8 word-cols
    const int img = blockIdx.x >> 4;
    const int band = blockIdx.x & 15;
    const int r0 = band * 16;
    const int imgbase = img * IMGPIX;

#pragma unroll 4
    for (int lr = 0; lr < 20; lr++) {
        int grow = r0 - 2 + lr;
        unsigned int word = 0u;
        if (grow >= 0 && grow < HH) {
            float v = tg[imgbase + grow * WW + wid * 32 + lane];
            word = __ballot_sync(0xffffffffu, v > 0.5f);
        }
        if (lane == 0) tgw[lr * 8 + wid] = word;
    }
    __syncthreads();
    if (tid < 160) {
        int wc = tid & 7;
        unsigned int c  = tgw[tid];
        unsigned int ml = (wc > 0) ? tgw[tid - 1] : 0u;
        unsigned int mr = (wc < 7) ? tgw[tid + 1] : 0u;
        unsigned int h = c;
        h |= (c << 1) | (ml >> 31);
        h |= (c << 2) | (ml >> 30);
        h |= (c >> 1) | (mr << 31);
        h |= (c >> 2) | (mr << 30);
        hw[tid] = h;
    }
    __syncthreads();
    if (tid < 128) {
        int rl = tid >> 3, wc = tid & 7;
        int lr = rl + 2;
        unsigned int f = hw[(lr - 2) * 8 + wc] | hw[(lr - 1) * 8 + wc] |
                         hw[lr * 8 + wc] |
                         hw[(lr + 1) * 8 + wc] | hw[(lr + 2) * 8 + wc];
        int gw = img * IMGWORDS + (r0 + rl) * 8 + wc;
        g_tgm[gw]  = tgw[lr * 8 + wc];
        g_fatm[gw] = f;
    }
}

// ---- K2: vertical two-pass distance scan per column (32 blocks x 256 thr) ----
// dynamic smem: fat words (8KB) + fwd distances u16 (128KB)
__global__ void __launch_bounds__(256, 1) k_vscan() {
    extern __shared__ unsigned int sm[];
    unsigned int* fat = sm;
    unsigned short* gf = reinterpret_cast<unsigned short*>(sm + IMGWORDS);
    __shared__ unsigned int s_or[8];
    const int tid = threadIdx.x;
    const int img = blockIdx.x;

    unsigned int any = 0u;
#pragma unroll
    for (int k = 0; k < 8; k++) {
        int w = tid + k * 256;
        unsigned int v = g_fatm[img * IMGWORDS + w];
        fat[w] = v; any |= v;
    }
    any = ior32(any);
    if ((tid & 31) == 0) s_or[tid >> 5] = any;
    __syncthreads();
    if (tid == 0) {
        unsigned int a = 0;
#pragma unroll
        for (int i = 0; i < 8; i++) a |= s_or[i];
        g_fg[img] = a ? 1 : 0;
    }

    const int j = tid;
    const int wsel = j >> 5, bsel = j & 31;
    int d = INF_I;
#pragma unroll 4
    for (int h = 0; h < HH; h++) {
        int bit = (fat[(h << 3) | wsel] >> bsel) & 1;
        d = bit ? min(d + 1, INF_I) : 0;
        gf[h * WW + j] = (unsigned short)d;
    }
    d = INF_I;
#pragma unroll 4
    for (int h = HH - 1; h >= 0; h--) {
        int bit = (fat[(h << 3) | wsel] >> bsel) & 1;
        d = bit ? min(d + 1, INF_I) : 0;
        int m = min((int)gf[h * WW + j], d);
        g_gv[img * IMGPIX + h * WW + j] = (unsigned short)m;
    }
}

// ---- K3: pruned horizontal min-plus, stores d2 + min/max partials ----
// 256 blocks (img x 8 bands of 32 rows) x 256 thr
__global__ void k_rowpass() {
    __shared__ unsigned short tile[32 * WW];
    __shared__ int smn[8], smx[8];
    const int tid = threadIdx.x;
    const int img = blockIdx.x >> 3;
    const int band = blockIdx.x & 7;
    const int base = img * IMGPIX + band * 32 * WW;

#pragma unroll 8
    for (int k = 0; k < 32; k++) tile[k * WW + tid] = g_gv[base + k * WW + tid];
    __syncthreads();

    int mn = 0x7fffffff, mx = 0;
#pragma unroll 1
    for (int r = 0; r < 32; r++) {
        const unsigned short* grow = tile + r * WW;
        int g0 = grow[tid];
        int best = g0 * g0;
        for (int rad = 1; rad < WW; rad++) {
            int r2 = rad * rad;
            if (r2 >= best) break;
            int jl = tid - rad, jr = tid + rad;
            if (jl >= 0) { int gv = grow[jl]; best = min(best, gv * gv + r2); }
            if (jr < WW) { int gv = grow[jr]; best = min(best, gv * gv + r2); }
        }
        g_d2[base + r * WW + tid] = (unsigned int)best;
        mn = min(mn, best); mx = max(mx, best);
    }
    mn = imin32(mn); mx = imax32(mx);
    if ((tid & 31) == 0) { smn[tid >> 5] = mn; smx[tid >> 5] = mx; }
    __syncthreads();
    if (tid == 0) {
        int a = smn[0], b = smx[0];
#pragma unroll
        for (int i = 1; i < 8; i++) { a = min(a, smn[i]); b = max(b, smx[i]); }
        g_bmin[blockIdx.x] = a; g_bmax[blockIdx.x] = b;
    }
}

// ---- K4: fused normalization + dice partials (2048 blocks x 256 thr) ----
__global__ void k_dice(const float* __restrict__ preds) {
    __shared__ float s_mn, s_inv;
    __shared__ int s_fg;
    __shared__ float sf[8];
    const int tid = threadIdx.x;
    const int img = blockIdx.x >> 6;       // 64 blocks per image

    if (tid == 0) {
        int mn = 0x7fffffff, mx = 0;
#pragma unroll
        for (int k = 0; k < 8; k++) {
            mn = min(mn, g_bmin[img * 8 + k]);
            mx = max(mx, g_bmax[img * 8 + k]);
        }
        float smn = 1.0f / (1.0f + __expf(-sqrtf((float)mn) * 0.2f));
        float smx = 1.0f / (1.0f + __expf(-sqrtf((float)mx) * 0.2f));
        float dd = smx - smn;
        s_mn = smn;
        s_inv = (dd > 0.0f) ? (1.0f / dd) : 1.0f;
        s_fg = g_fg[img];
    }
    __syncthreads();

    const float mn = s_mn, inv = s_inv;
    const int fg = s_fg;
    float inter = 0.0f, card = 0.0f, tsum = 0.0f;
    const int base = blockIdx.x * 1024;
#pragma unroll
    for (int k = 0; k < 4; k++) {
        int idx = base + k * 256 + tid;
        int wsel = idx >> 5, bsel = idx & 31;
        float t = (float)((g_tgm[wsel] >> bsel) & 1u);
        float p = 1.0f / (1.0f + __expf(-preds[idx]));
        float dm;
        if (fg) {
            float dist = sqrtf((float)g_d2[idx]);
            float soft = 1.0f / (1.0f + __expf(-dist * 0.2f));
            float fatb = (float)((g_fatm[wsel] >> bsel) & 1u);
            dm = (soft - mn) * inv + (1.0f - fatb) * 0.1f;
        } else {
            dm = 1.0f - t;
        }
        float pw = p * dm;
        inter += pw * t;
        card  += pw + t;
        tsum  += t;
    }
    inter = fsum32(inter);
    if ((tid & 31) == 0) sf[tid >> 5] = inter;
    __syncthreads();
    if (tid == 0) { float a = 0;
#pragma unroll
        for (int i = 0; i < 8; i++) a += sf[i];
        g_pi[blockIdx.x] = a; }
    __syncthreads();
    card = fsum32(card);
    if ((tid & 31) == 0) sf[tid >> 5] = card;
    __syncthreads();
    if (tid == 0) { float a = 0;
#pragma unroll
        for (int i = 0; i < 8; i++) a += sf[i];
        g_pc[blockIdx.x] = a; }
    __syncthreads();
    tsum = fsum32(tsum);
    if ((tid & 31) == 0) sf[tid >> 5] = tsum;
    __syncthreads();
    if (tid == 0) { float a = 0;
#pragma unroll
        for (int i = 0; i < 8; i++) a += sf[i];
        g_pt[blockIdx.x] = a; }
}

// ---- K5: deterministic final reduce ----
__global__ void k_out(float* out) {
    __shared__ float si[256], sc[256], st[256];
    int j = threadIdx.x;
    float inter = 0, card = 0, tsum = 0;
    for (int k = j; k < DICE_BLOCKS; k += 256) {
        inter += g_pi[k]; card += g_pc[k]; tsum += g_pt[k];
    }
    si[j] = inter; sc[j] = card; st[j] = tsum;
    __syncthreads();
#pragma unroll
    for (int s = 128; s > 0; s >>= 1) {
        if (j < s) { si[j] += si[j + s]; sc[j] += sc[j + s]; st[j] += st[j + s]; }
        __syncthreads();
    }
    if (j == 0) {
        float dice = 2.0f * si[0] / fmaxf(sc[0], 1e-7f);
        float loss = 1.0f - dice;
        out[0] = (st[0] > 0.0f) ? loss : 0.0f;
    }
}

extern "C" void kernel_launch(void* const* d_in, const int* in_sizes, int n_in,
                              void* d_out, int out_size) {
    const float* preds = (const float*)d_in[0];
    const float* tg    = (const float*)d_in[1];
    float* out = (float*)d_out;

    const int vs_smem = IMGWORDS * 4 + IMGPIX * 2;   // 8KB + 128KB
    cudaFuncSetAttribute(k_vscan, cudaFuncAttributeMaxDynamicSharedMemorySize, vs_smem);

    k_dilate<<<512, 256>>>(tg);
    k_vscan<<<BATCH, 256, vs_smem>>>();
    k_rowpass<<<ROW_BLOCKS, 256>>>();
    k_dice<<<DICE_BLOCKS, 256>>>(preds);
    k_out<<<1, 256>>>(out);
}